// round 1
// baseline (speedup 1.0000x reference)
#include <cuda_runtime.h>
#include <cuda_bf16.h>
#include <cstdint>

// Problem constants
#define BB 4
#define TT 2048
#define CC 1024
#define HH 16
#define HS 64
#define MM (BB * TT)   // 8192

// Scratch buffers (device globals: allocation-free)
__device__ float g_q[BB * HH * TT * HS];
__device__ float g_k[BB * HH * TT * HS];
__device__ float g_v[BB * HH * TT * HS];
__device__ float g_y[MM * CC];

// ---------------------------------------------------------------------------
// GEMM: out = A[M,K] @ W[N,K]^T + bias[N]
// 128x128 tile, Ktile=16, 256 threads, 8x8 micro-tile.
// OUTMODE 0: out[m*N + n] (row-major [M,N])
// OUTMODE 1: out[((b*H + h)*T + t)*HS + d]  (q/k/v layout [B,H,T,HS])
// ---------------------------------------------------------------------------
template <int OUTMODE>
__global__ __launch_bounds__(256) void gemm_kernel(
    const float* __restrict__ A, const float* __restrict__ W,
    const float* __restrict__ bias, float* __restrict__ out)
{
    __shared__ float As[16][132];
    __shared__ float Bs[16][132];

    const int tid = threadIdx.x;
    const int tx = tid & 15;
    const int ty = tid >> 4;
    const int m0 = blockIdx.y * 128;
    const int n0 = blockIdx.x * 128;
    const int lr = tid >> 2;
    const int lq = (tid & 3) * 4;

    float acc[8][8];
#pragma unroll
    for (int i = 0; i < 8; i++)
#pragma unroll
        for (int j = 0; j < 8; j++) acc[i][j] = 0.0f;

    for (int k0 = 0; k0 < CC; k0 += 16) {
#pragma unroll
        for (int h = 0; h < 2; h++) {
            int r = lr + 64 * h;
            float4 a = *(const float4*)(A + (size_t)(m0 + r) * CC + k0 + lq);
            As[lq + 0][r] = a.x; As[lq + 1][r] = a.y;
            As[lq + 2][r] = a.z; As[lq + 3][r] = a.w;
            float4 b = *(const float4*)(W + (size_t)(n0 + r) * CC + k0 + lq);
            Bs[lq + 0][r] = b.x; Bs[lq + 1][r] = b.y;
            Bs[lq + 2][r] = b.z; Bs[lq + 3][r] = b.w;
        }
        __syncthreads();
#pragma unroll
        for (int k = 0; k < 16; k++) {
            float4 a0 = *(const float4*)&As[k][ty * 8];
            float4 a1 = *(const float4*)&As[k][ty * 8 + 4];
            float4 b0 = *(const float4*)&Bs[k][tx * 8];
            float4 b1 = *(const float4*)&Bs[k][tx * 8 + 4];
            float av[8] = {a0.x, a0.y, a0.z, a0.w, a1.x, a1.y, a1.z, a1.w};
            float bv[8] = {b0.x, b0.y, b0.z, b0.w, b1.x, b1.y, b1.z, b1.w};
#pragma unroll
            for (int i = 0; i < 8; i++)
#pragma unroll
                for (int j = 0; j < 8; j++) acc[i][j] += av[i] * bv[j];
        }
        __syncthreads();
    }

#pragma unroll
    for (int i = 0; i < 8; i++) {
        int m = m0 + ty * 8 + i;
#pragma unroll
        for (int j = 0; j < 8; j++) {
            int n = n0 + tx * 8 + j;
            float v = acc[i][j] + bias[n];
            if (OUTMODE == 0) {
                out[(size_t)m * CC + n] = v;
            } else {
                int b = m >> 11;       // m / T
                int t = m & (TT - 1);
                int h2 = n >> 6;       // n / HS
                int d = n & (HS - 1);
                out[(((size_t)(b * HH + h2)) * TT + t) * HS + d] = v;
            }
        }
    }
}

// ---------------------------------------------------------------------------
// Flash-attention (causal, fp32, online softmax)
// Block: 256 threads handling BM=64 queries x BN=64 keys per tile, HS=64.
// grid = (T/64, B*H).  Output written as [B,T,C] into g_y.
// ---------------------------------------------------------------------------
#define APAD 68

__global__ __launch_bounds__(256) void attn_kernel(
    const float* __restrict__ Q, const float* __restrict__ K,
    const float* __restrict__ V, float* __restrict__ Y)
{
    extern __shared__ float sm[];
    float (*Qs)[APAD] = (float(*)[APAD])(sm);
    float (*Ks)[APAD] = (float(*)[APAD])(sm + 64 * APAD);
    float (*Vs)[APAD] = (float(*)[APAD])(sm + 2 * 64 * APAD);
    float (*Ps)[APAD] = (float(*)[APAD])(sm + 3 * 64 * APAD);

    const int tid = threadIdx.x;
    const int tx = tid & 15;
    const int ty = tid >> 4;
    const int bh = blockIdx.y;
    const int qt = blockIdx.x;
    const int m0 = qt * 64;

    const float* Qb = Q + (size_t)bh * TT * HS;
    const float* Kb = K + (size_t)bh * TT * HS;
    const float* Vb = V + (size_t)bh * TT * HS;

    // Load Q tile [64,64]
    {
        int r = tid >> 2;
        int c = (tid & 3) * 16;
#pragma unroll
        for (int u = 0; u < 4; u++) {
            *(float4*)&Qs[r][c + u * 4] =
                *(const float4*)(Qb + (size_t)(m0 + r) * HS + c + u * 4);
        }
    }

    float mrow[4], lrow[4], acc[4][4];
#pragma unroll
    for (int i = 0; i < 4; i++) {
        mrow[i] = -1e30f;
        lrow[i] = 0.0f;
#pragma unroll
        for (int j = 0; j < 4; j++) acc[i][j] = 0.0f;
    }

    const float scale = 0.125f;  // 1/sqrt(64)

    for (int kt = 0; kt <= qt; kt++) {
        const int n0b = kt * 64;
        __syncthreads();  // prior PV / Q load complete before K/V overwrite
        {
            int r = tid >> 2;
            int c = (tid & 3) * 16;
#pragma unroll
            for (int u = 0; u < 4; u++) {
                *(float4*)&Ks[r][c + u * 4] =
                    *(const float4*)(Kb + (size_t)(n0b + r) * HS + c + u * 4);
                *(float4*)&Vs[r][c + u * 4] =
                    *(const float4*)(Vb + (size_t)(n0b + r) * HS + c + u * 4);
            }
        }
        __syncthreads();

        // S = Q K^T for 4x4 micro-tile
        float s[4][4];
#pragma unroll
        for (int i = 0; i < 4; i++)
#pragma unroll
            for (int j = 0; j < 4; j++) s[i][j] = 0.0f;

#pragma unroll
        for (int d = 0; d < HS; d += 4) {
            float4 a[4], b[4];
#pragma unroll
            for (int i = 0; i < 4; i++) a[i] = *(const float4*)&Qs[ty * 4 + i][d];
#pragma unroll
            for (int j = 0; j < 4; j++) b[j] = *(const float4*)&Ks[tx * 4 + j][d];
#pragma unroll
            for (int i = 0; i < 4; i++)
#pragma unroll
                for (int j = 0; j < 4; j++) {
                    s[i][j] += a[i].x * b[j].x + a[i].y * b[j].y +
                               a[i].z * b[j].z + a[i].w * b[j].w;
                }
        }

#pragma unroll
        for (int i = 0; i < 4; i++)
#pragma unroll
            for (int j = 0; j < 4; j++) s[i][j] *= scale;

        if (kt == qt) {  // causal mask only needed on the diagonal tile
#pragma unroll
            for (int i = 0; i < 4; i++)
#pragma unroll
                for (int j = 0; j < 4; j++) {
                    if (n0b + tx * 4 + j > m0 + ty * 4 + i) s[i][j] = -1e30f;
                }
        }

        // online softmax (row groups are 16 contiguous lanes sharing ty)
#pragma unroll
        for (int i = 0; i < 4; i++) {
            float rm = fmaxf(fmaxf(s[i][0], s[i][1]), fmaxf(s[i][2], s[i][3]));
#pragma unroll
            for (int o = 8; o >= 1; o >>= 1)
                rm = fmaxf(rm, __shfl_xor_sync(0xffffffffu, rm, o));
            float mnew = fmaxf(mrow[i], rm);
            float corr = __expf(mrow[i] - mnew);
            mrow[i] = mnew;
            float rs = 0.0f;
#pragma unroll
            for (int j = 0; j < 4; j++) {
                float p = __expf(s[i][j] - mnew);
                s[i][j] = p;
                rs += p;
            }
#pragma unroll
            for (int o = 8; o >= 1; o >>= 1)
                rs += __shfl_xor_sync(0xffffffffu, rs, o);
            lrow[i] = lrow[i] * corr + rs;
#pragma unroll
            for (int j = 0; j < 4; j++) acc[i][j] *= corr;
        }

        // stage P into smem for the PV GEMM
#pragma unroll
        for (int i = 0; i < 4; i++)
#pragma unroll
            for (int j = 0; j < 4; j++) Ps[ty * 4 + i][tx * 4 + j] = s[i][j];
        __syncthreads();

        // acc += P @ V
#pragma unroll 8
        for (int ss = 0; ss < 64; ss++) {
            float4 vv = *(const float4*)&Vs[ss][tx * 4];
            float p0 = Ps[ty * 4 + 0][ss];
            float p1 = Ps[ty * 4 + 1][ss];
            float p2 = Ps[ty * 4 + 2][ss];
            float p3 = Ps[ty * 4 + 3][ss];
            acc[0][0] += p0 * vv.x; acc[0][1] += p0 * vv.y;
            acc[0][2] += p0 * vv.z; acc[0][3] += p0 * vv.w;
            acc[1][0] += p1 * vv.x; acc[1][1] += p1 * vv.y;
            acc[1][2] += p1 * vv.z; acc[1][3] += p1 * vv.w;
            acc[2][0] += p2 * vv.x; acc[2][1] += p2 * vv.y;
            acc[2][2] += p2 * vv.z; acc[2][3] += p2 * vv.w;
            acc[3][0] += p3 * vv.x; acc[3][1] += p3 * vv.y;
            acc[3][2] += p3 * vv.z; acc[3][3] += p3 * vv.w;
        }
    }

    // write y as [B,T,C] (head-concat layout)
    const int b = bh >> 4;
    const int h = bh & 15;
#pragma unroll
    for (int i = 0; i < 4; i++) {
        float inv = 1.0f / lrow[i];
        int t = m0 + ty * 4 + i;
#pragma unroll
        for (int j = 0; j < 4; j++) {
            Y[((size_t)b * TT + t) * CC + h * HS + tx * 4 + j] = acc[i][j] * inv;
        }
    }
}

// ---------------------------------------------------------------------------
extern "C" void kernel_launch(void* const* d_in, const int* in_sizes, int n_in,
                              void* d_out, int out_size)
{
    const float* x  = (const float*)d_in[0];
    const float* Wq = (const float*)d_in[1];
    const float* bq = (const float*)d_in[2];
    const float* Wk = (const float*)d_in[3];
    const float* bk = (const float*)d_in[4];
    const float* Wv = (const float*)d_in[5];
    const float* bv = (const float*)d_in[6];
    const float* Wp = (const float*)d_in[7];
    const float* bp = (const float*)d_in[8];
    float* out = (float*)d_out;

    float *q, *k, *v, *y;
    cudaGetSymbolAddress((void**)&q, g_q);
    cudaGetSymbolAddress((void**)&k, g_k);
    cudaGetSymbolAddress((void**)&v, g_v);
    cudaGetSymbolAddress((void**)&y, g_y);

    dim3 ggrid(CC / 128, MM / 128);   // (8, 64)
    gemm_kernel<1><<<ggrid, 256>>>(x, Wq, bq, q);
    gemm_kernel<1><<<ggrid, 256>>>(x, Wk, bk, k);
    gemm_kernel<1><<<ggrid, 256>>>(x, Wv, bv, v);

    const int attn_smem = 4 * 64 * APAD * sizeof(float);  // 69632 B
    cudaFuncSetAttribute(attn_kernel, cudaFuncAttributeMaxDynamicSharedMemorySize,
                         attn_smem);
    dim3 agrid(TT / 64, BB * HH);     // (32, 64)
    attn_kernel<<<agrid, 256, attn_smem>>>(q, k, v, y);

    gemm_kernel<0><<<ggrid, 256>>>(y, Wp, bp, out);
}